// round 1
// baseline (speedup 1.0000x reference)
#include <cuda_runtime.h>

// Problem constants
#define B_     2
#define L2_    4
#define N2_    2048
#define L1_    9
#define N1_    8192
#define CIN_   128
#define CT_    128
#define CS_    256
#define CORIG_ 64
#define KK_    3
#define KD3_   192   // CT_ + CORIG_

// Scratch (static device globals — no runtime allocation)
__device__ float g_h   [B_*L2_*KK_*CT_*N2_];   // stage-1 output, [z][o][n]
__device__ float g_tt  [B_*L2_*KK_*N2_*CT_];   // stage-2 output, n-major [z][n][o]
__device__ float g_bcat[B_*L1_*N1_*CT_];       // interp output, [q][c] (c contiguous)
__device__ int   g_off [B_*L1_*N1_*3];         // gather offsets into g_tt
__device__ float g_w   [B_*L1_*N1_*3];         // normalized inverse-distance weights

// ---------------------------------------------------------------------------
// Stage 1: h = relu(Wt0[k] @ features[b,l]),  24 x (128x128x2048)
// ---------------------------------------------------------------------------
__global__ __launch_bounds__(256) void k_gemm1(const float* __restrict__ Wt0,
                                               const float* __restrict__ F)
{
    const int z  = blockIdx.z;      // (b*4+l)*3 + k
    const int k  = z % 3;
    const int bl = z / 3;
    const float* A  = Wt0 + k  * CT_ * CIN_;
    const float* Bm = F   + bl * CIN_ * N2_;
    float* C = g_h + (size_t)z * CT_ * N2_;
    const int nb = blockIdx.x * 128;

    __shared__ float As[16][132];
    __shared__ float Bs[16][132];

    const int tid = threadIdx.x;
    const int tx = tid & 15;
    const int ty = tid >> 4;

    float acc[8][8];
#pragma unroll
    for (int i = 0; i < 8; i++)
#pragma unroll
        for (int j = 0; j < 8; j++) acc[i][j] = 0.f;

    for (int k0 = 0; k0 < CIN_; k0 += 16) {
#pragma unroll
        for (int i = 0; i < 8; i++) {
            int e = i * 256 + tid;
            int m = e >> 4, kk = e & 15;
            As[kk][m] = A[m * CIN_ + k0 + kk];
        }
#pragma unroll
        for (int i = 0; i < 8; i++) {
            int e = i * 256 + tid;
            int n = e & 127, kk = e >> 7;
            Bs[kk][n] = Bm[(k0 + kk) * N2_ + nb + n];
        }
        __syncthreads();
#pragma unroll
        for (int kk = 0; kk < 16; kk++) {
            float4 a0 = *(const float4*)&As[kk][ty * 4];
            float4 a1 = *(const float4*)&As[kk][64 + ty * 4];
            float4 b0 = *(const float4*)&Bs[kk][tx * 4];
            float4 b1 = *(const float4*)&Bs[kk][64 + tx * 4];
            float ar[8] = {a0.x,a0.y,a0.z,a0.w,a1.x,a1.y,a1.z,a1.w};
            float br[8] = {b0.x,b0.y,b0.z,b0.w,b1.x,b1.y,b1.z,b1.w};
#pragma unroll
            for (int i = 0; i < 8; i++)
#pragma unroll
                for (int j = 0; j < 8; j++)
                    acc[i][j] += ar[i] * br[j];
        }
        __syncthreads();
    }

#pragma unroll
    for (int i = 0; i < 8; i++) {
        int m = (i < 4) ? (ty * 4 + i) : (64 + ty * 4 + i - 4);
        float4 v0 = make_float4(fmaxf(acc[i][0],0.f), fmaxf(acc[i][1],0.f),
                                fmaxf(acc[i][2],0.f), fmaxf(acc[i][3],0.f));
        float4 v1 = make_float4(fmaxf(acc[i][4],0.f), fmaxf(acc[i][5],0.f),
                                fmaxf(acc[i][6],0.f), fmaxf(acc[i][7],0.f));
        *(float4*)&C[m * N2_ + nb + tx * 4]      = v0;
        *(float4*)&C[m * N2_ + nb + 64 + tx * 4] = v1;
    }
}

// ---------------------------------------------------------------------------
// Stage 2: tt = relu(Wt1[k] @ h[b,l,k]), output TRANSPOSED to n-major [z][n][o]
// ---------------------------------------------------------------------------
__global__ __launch_bounds__(256) void k_gemm2(const float* __restrict__ Wt1)
{
    const int z = blockIdx.z;
    const int k = z % 3;
    const float* A  = Wt1 + k * CT_ * CT_;
    const float* Bm = g_h + (size_t)z * CT_ * N2_;
    float* C = g_tt + (size_t)z * N2_ * CT_;
    const int nb = blockIdx.x * 128;

    __shared__ float As[16][132];
    __shared__ float Bs[16][132];

    const int tid = threadIdx.x;
    const int tx = tid & 15;
    const int ty = tid >> 4;

    float acc[8][8];
#pragma unroll
    for (int i = 0; i < 8; i++)
#pragma unroll
        for (int j = 0; j < 8; j++) acc[i][j] = 0.f;

    for (int k0 = 0; k0 < CT_; k0 += 16) {
#pragma unroll
        for (int i = 0; i < 8; i++) {
            int e = i * 256 + tid;
            int m = e >> 4, kk = e & 15;
            As[kk][m] = A[m * CT_ + k0 + kk];
        }
#pragma unroll
        for (int i = 0; i < 8; i++) {
            int e = i * 256 + tid;
            int n = e & 127, kk = e >> 7;
            Bs[kk][n] = Bm[(k0 + kk) * N2_ + nb + n];
        }
        __syncthreads();
#pragma unroll
        for (int kk = 0; kk < 16; kk++) {
            float4 a0 = *(const float4*)&As[kk][ty * 4];
            float4 a1 = *(const float4*)&As[kk][64 + ty * 4];
            float4 b0 = *(const float4*)&Bs[kk][tx * 4];
            float4 b1 = *(const float4*)&Bs[kk][64 + tx * 4];
            float ar[8] = {a0.x,a0.y,a0.z,a0.w,a1.x,a1.y,a1.z,a1.w};
            float br[8] = {b0.x,b0.y,b0.z,b0.w,b1.x,b1.y,b1.z,b1.w};
#pragma unroll
            for (int i = 0; i < 8; i++)
#pragma unroll
                for (int j = 0; j < 8; j++)
                    acc[i][j] += ar[i] * br[j];
        }
        __syncthreads();
    }

    // transposed write: C[n][o]
#pragma unroll
    for (int j = 0; j < 8; j++) {
        int n = (j < 4) ? (tx * 4 + j) : (64 + tx * 4 + j - 4);
        float* Cp = C + (size_t)(nb + n) * CT_;
        float4 v0 = make_float4(fmaxf(acc[0][j],0.f), fmaxf(acc[1][j],0.f),
                                fmaxf(acc[2][j],0.f), fmaxf(acc[3][j],0.f));
        float4 v1 = make_float4(fmaxf(acc[4][j],0.f), fmaxf(acc[5][j],0.f),
                                fmaxf(acc[6][j],0.f), fmaxf(acc[7][j],0.f));
        *(float4*)&Cp[ty * 4]      = v0;
        *(float4*)&Cp[64 + ty * 4] = v1;
    }
}

// ---------------------------------------------------------------------------
// KNN: per (b,t1,n1) find top-3 nearest seeds, store weights + gather offsets
// ---------------------------------------------------------------------------
__global__ __launch_bounds__(256) void k_knn(const float* __restrict__ xyzs,
                                             const float* __restrict__ oxyzs)
{
    const int bt  = blockIdx.y;          // b*9 + (t1-1)
    const int bq  = bt / 9;
    const int t1  = bt % 9 + 1;
    const int n   = blockIdx.x * 256 + threadIdx.x;
    const int tid = threadIdx.x;

    // contributing (t2, k) segments, in t2-ascending order (matches concat)
    int t2s[2], ks[2], nseg = 0;
    if ((t1 & 1) == 0) { t2s[0] = t1 / 2 - 1; ks[0] = 1; nseg = 1; }
    else {
        int p = (t1 - 1) >> 1;
        if (p - 1 >= 0) { t2s[nseg] = p - 1; ks[nseg] = 2; nseg++; }
        if (p <= 3)     { t2s[nseg] = p;     ks[nseg] = 0; nseg++; }
    }

    const float* q = oxyzs + ((size_t)bt * N1_ + n) * 3;
    const float qx = q[0], qy = q[1], qz = q[2];

    __shared__ float sr[3 * 1024];
    float b0 = 3.4e38f, b1 = 3.4e38f, b2 = 3.4e38f;
    int   o0 = 0, o1 = 0, o2 = 0;

    for (int s = 0; s < nseg; s++) {
        const float* sp = xyzs + (size_t)(bq * 4 + t2s[s]) * N2_ * 3;
        const int offbase = ((bq * 4 + t2s[s]) * 3 + ks[s]) * (N2_ * CT_);
        for (int base = 0; base < N2_; base += 1024) {
            __syncthreads();
#pragma unroll
            for (int t = tid; t < 3072; t += 256) sr[t] = sp[base * 3 + t];
            __syncthreads();
            for (int t = 0; t < 1024; t++) {
                float dx = qx - sr[3 * t];
                float dy = qy - sr[3 * t + 1];
                float dz = qz - sr[3 * t + 2];
                float d = dx * dx + dy * dy + dz * dz;
                if (d < b2) {
                    int off = offbase + (base + t) * CT_;
                    if (d < b1) {
                        b2 = b1; o2 = o1;
                        if (d < b0) { b1 = b0; o1 = o0; b0 = d; o0 = off; }
                        else        { b1 = d; o1 = off; }
                    } else { b2 = d; o2 = off; }
                }
            }
        }
    }

    float w0 = 1.f / (b0 + 1e-8f);
    float w1 = 1.f / (b1 + 1e-8f);
    float w2 = 1.f / (b2 + 1e-8f);
    float si = 1.f / (w0 + w1 + w2);
    const int base3 = (bt * N1_ + n) * 3;
    g_w[base3]     = w0 * si;
    g_w[base3 + 1] = w1 * si;
    g_w[base3 + 2] = w2 * si;
    g_off[base3]     = o0;
    g_off[base3 + 1] = o1;
    g_off[base3 + 2] = o2;
}

// ---------------------------------------------------------------------------
// Interp: g_bcat[q][c] = sum_j w_j * tt[off_j + c]   (coalesced 512B gathers)
// ---------------------------------------------------------------------------
__global__ void k_interp()
{
    const int gq = blockIdx.x * 4 + threadIdx.y;   // 0 .. 18*8192-1
    const int c  = threadIdx.x;                    // 0..127
    const int b3 = gq * 3;
    const float w0 = g_w[b3], w1 = g_w[b3 + 1], w2 = g_w[b3 + 2];
    const int   o0 = g_off[b3], o1 = g_off[b3 + 1], o2 = g_off[b3 + 2];
    g_bcat[(size_t)gq * CT_ + c] =
        w0 * g_tt[o0 + c] + w1 * g_tt[o1 + c] + w2 * g_tt[o2 + c];
}

// ---------------------------------------------------------------------------
// Stage 3: out = relu(bn(Ws @ concat(interp, orig_feats)))
//   18 x (256 x 192 x 8192). K<128 from g_bcat (n-major), K>=128 from OF.
// ---------------------------------------------------------------------------
__global__ __launch_bounds__(256) void k_gemm3(
    const float* __restrict__ Ws, const float* __restrict__ OF,
    const float* __restrict__ gamma, const float* __restrict__ beta,
    const float* __restrict__ mean,  const float* __restrict__ var,
    float* __restrict__ out)
{
    const int bt = blockIdx.z;           // 0..17
    const int m0 = blockIdx.y * 128;     // 0 or 128
    const int nb = blockIdx.x * 128;
    const float* A  = Ws + m0 * KD3_;
    const float* Bt = g_bcat + (size_t)bt * N1_ * CT_;

    __shared__ float As[16][132];
    __shared__ float Bs[16][132];

    const int tid = threadIdx.x;
    const int tx = tid & 15;
    const int ty = tid >> 4;

    float acc[8][8];
#pragma unroll
    for (int i = 0; i < 8; i++)
#pragma unroll
        for (int j = 0; j < 8; j++) acc[i][j] = 0.f;

    for (int k0 = 0; k0 < KD3_; k0 += 16) {
#pragma unroll
        for (int i = 0; i < 8; i++) {
            int e = i * 256 + tid;
            int m = e >> 4, kk = e & 15;
            As[kk][m] = A[m * KD3_ + k0 + kk];
        }
        if (k0 < CT_) {
            // interp part, n-major: Bt[n][c]
#pragma unroll
            for (int i = 0; i < 8; i++) {
                int e = i * 256 + tid;
                int kk = e & 15, n = e >> 4;
                Bs[kk][n] = Bt[(size_t)(nb + n) * CT_ + k0 + kk];
            }
        } else {
            // original_features part, c-major: OF[(bt*64 + c)*N1 + n]
            const float* OFp = OF + ((size_t)bt * CORIG_ + (k0 - CT_)) * N1_ + nb;
#pragma unroll
            for (int i = 0; i < 8; i++) {
                int e = i * 256 + tid;
                int n = e & 127, kk = e >> 7;
                Bs[kk][n] = OFp[(size_t)kk * N1_ + n];
            }
        }
        __syncthreads();
#pragma unroll
        for (int kk = 0; kk < 16; kk++) {
            float4 a0 = *(const float4*)&As[kk][ty * 4];
            float4 a1 = *(const float4*)&As[kk][64 + ty * 4];
            float4 b0 = *(const float4*)&Bs[kk][tx * 4];
            float4 b1 = *(const float4*)&Bs[kk][64 + tx * 4];
            float ar[8] = {a0.x,a0.y,a0.z,a0.w,a1.x,a1.y,a1.z,a1.w};
            float br[8] = {b0.x,b0.y,b0.z,b0.w,b1.x,b1.y,b1.z,b1.w};
#pragma unroll
            for (int i = 0; i < 8; i++)
#pragma unroll
                for (int j = 0; j < 8; j++)
                    acc[i][j] += ar[i] * br[j];
        }
        __syncthreads();
    }

#pragma unroll
    for (int i = 0; i < 8; i++) {
        int m = m0 + ((i < 4) ? (ty * 4 + i) : (64 + ty * 4 + i - 4));
        float sc = gamma[m] * rsqrtf(var[m] + 1e-5f);
        float bi = beta[m] - mean[m] * sc;
        float* Cp = out + ((size_t)bt * CS_ + m) * N1_ + nb;
        float4 v0 = make_float4(fmaxf(acc[i][0]*sc+bi,0.f), fmaxf(acc[i][1]*sc+bi,0.f),
                                fmaxf(acc[i][2]*sc+bi,0.f), fmaxf(acc[i][3]*sc+bi,0.f));
        float4 v1 = make_float4(fmaxf(acc[i][4]*sc+bi,0.f), fmaxf(acc[i][5]*sc+bi,0.f),
                                fmaxf(acc[i][6]*sc+bi,0.f), fmaxf(acc[i][7]*sc+bi,0.f));
        *(float4*)&Cp[tx * 4]      = v0;
        *(float4*)&Cp[64 + tx * 4] = v1;
    }
}

// ---------------------------------------------------------------------------
extern "C" void kernel_launch(void* const* d_in, const int* in_sizes, int n_in,
                              void* d_out, int out_size)
{
    const float* xyzs   = (const float*)d_in[0];
    const float* oxyzs  = (const float*)d_in[1];
    const float* feats  = (const float*)d_in[2];
    const float* ofeats = (const float*)d_in[3];
    const float* Wt0    = (const float*)d_in[4];
    const float* Wt1    = (const float*)d_in[5];
    const float* Ws     = (const float*)d_in[6];
    const float* gamma  = (const float*)d_in[7];
    const float* beta   = (const float*)d_in[8];
    const float* mean   = (const float*)d_in[9];
    const float* var    = (const float*)d_in[10];

    const int NEWF = B_ * L1_ * CS_ * N1_;   // 37,748,736
    int ofs = out_size - NEWF;               // expect 442,368 (original_xyzs) or 0
    float* outF = (float*)d_out;
    if (ofs > 0) {
        cudaMemcpyAsync(d_out, d_in[1], (size_t)ofs * sizeof(float),
                        cudaMemcpyDeviceToDevice, 0);
        outF += ofs;
    }

    k_gemm1<<<dim3(16, 1, 24), 256>>>(Wt0, feats);
    k_gemm2<<<dim3(16, 1, 24), 256>>>(Wt1);
    k_knn<<<dim3(32, 18), 256>>>(xyzs, oxyzs);
    k_interp<<<B_ * L1_ * N1_ / 4, dim3(128, 4)>>>();
    k_gemm3<<<dim3(64, 2, 18), 256>>>(Ws, ofeats, gamma, beta, mean, var, outF);
}

// round 2
// speedup vs baseline: 1.0853x; 1.0853x over previous
#include <cuda_runtime.h>

// Problem constants
#define B_     2
#define L2_    4
#define N2_    2048
#define L1_    9
#define N1_    8192
#define CIN_   128
#define CT_    128
#define CS_    256
#define CORIG_ 64
#define KK_    3
#define KD3_   192   // CT_ + CORIG_

// Scratch (static device globals — no runtime allocation)
__device__ float g_h   [B_*L2_*KK_*CT_*N2_];   // stage-1 output, [z][o][n]
__device__ float g_tt  [B_*L2_*KK_*N2_*CT_];   // stage-2 output, n-major [z][n][o]
__device__ float g_bcat[B_*L1_*N1_*CT_];       // interp output, [q][c] (c contiguous)
__device__ int   g_off [B_*L1_*N1_*3];         // gather offsets into g_tt
__device__ float g_w   [B_*L1_*N1_*3];         // normalized inverse-distance weights

// ---- packed f32x2 helpers (FFMA2 — 2 FMAs per issue slot) --------------
__device__ __forceinline__ unsigned long long dup2(float x) {
    unsigned long long r;
    asm("mov.b64 %0, {%1, %1};" : "=l"(r) : "f"(x));
    return r;
}
__device__ __forceinline__ void ffma2(unsigned long long& d,
                                      unsigned long long a,
                                      unsigned long long b) {
    asm("fma.rn.f32x2 %0, %1, %2, %0;" : "+l"(d) : "l"(a), "l"(b));
}
union F4U  { float4 f4; unsigned long long u[2]; };
union U2F  { unsigned long long u; float2 f; };

// Shared inner product macro body: 16 k-steps, acc[8][4] packed pairs.
// Bs pair j covers old columns (2j, 2j+1).
#define MMA_KSTEP(kk)                                                        \
    {                                                                        \
        float4 a0 = *(const float4*)&As[kk][ty * 4];                         \
        float4 a1 = *(const float4*)&As[kk][64 + ty * 4];                    \
        F4U b0, b1;                                                          \
        b0.f4 = *(const float4*)&Bs[kk][tx * 4];                             \
        b1.f4 = *(const float4*)&Bs[kk][64 + tx * 4];                        \
        unsigned long long ad[8] = {dup2(a0.x), dup2(a0.y), dup2(a0.z),      \
                                    dup2(a0.w), dup2(a1.x), dup2(a1.y),      \
                                    dup2(a1.z), dup2(a1.w)};                 \
        unsigned long long bd[4] = {b0.u[0], b0.u[1], b1.u[0], b1.u[1]};     \
        _Pragma("unroll")                                                    \
        for (int i = 0; i < 8; i++) {                                        \
            _Pragma("unroll")                                                \
            for (int j = 0; j < 4; j++) ffma2(acc[i][j], ad[i], bd[j]);      \
        }                                                                    \
    }

// ---------------------------------------------------------------------------
// Stage 1: h = relu(Wt0[k] @ features[b,l]),  24 x (128x128x2048)
// ---------------------------------------------------------------------------
__global__ __launch_bounds__(256) void k_gemm1(const float* __restrict__ Wt0,
                                               const float* __restrict__ F)
{
    const int z  = blockIdx.z;      // (b*4+l)*3 + k
    const int k  = z % 3;
    const int bl = z / 3;
    const float* A  = Wt0 + k  * CT_ * CIN_;
    const float* Bm = F   + bl * CIN_ * N2_;
    float* C = g_h + (size_t)z * CT_ * N2_;
    const int nb = blockIdx.x * 128;

    __shared__ float As[16][132];
    __shared__ float Bs[16][132];

    const int tid = threadIdx.x;
    const int tx = tid & 15;
    const int ty = tid >> 4;

    unsigned long long acc[8][4];
#pragma unroll
    for (int i = 0; i < 8; i++)
#pragma unroll
        for (int j = 0; j < 4; j++) acc[i][j] = 0ull;

    for (int k0 = 0; k0 < CIN_; k0 += 16) {
#pragma unroll
        for (int i = 0; i < 8; i++) {
            int e = i * 256 + tid;
            int m = e >> 4, kk = e & 15;
            As[kk][m] = A[m * CIN_ + k0 + kk];
        }
#pragma unroll
        for (int i = 0; i < 8; i++) {
            int e = i * 256 + tid;
            int n = e & 127, kk = e >> 7;
            Bs[kk][n] = Bm[(k0 + kk) * N2_ + nb + n];
        }
        __syncthreads();
#pragma unroll
        for (int kk = 0; kk < 16; kk++) MMA_KSTEP(kk)
        __syncthreads();
    }

#pragma unroll
    for (int i = 0; i < 8; i++) {
        int m = (i < 4) ? (ty * 4 + i) : (64 + ty * 4 + i - 4);
        U2F p0, p1, p2, p3;
        p0.u = acc[i][0]; p1.u = acc[i][1]; p2.u = acc[i][2]; p3.u = acc[i][3];
        float4 v0 = make_float4(fmaxf(p0.f.x,0.f), fmaxf(p0.f.y,0.f),
                                fmaxf(p1.f.x,0.f), fmaxf(p1.f.y,0.f));
        float4 v1 = make_float4(fmaxf(p2.f.x,0.f), fmaxf(p2.f.y,0.f),
                                fmaxf(p3.f.x,0.f), fmaxf(p3.f.y,0.f));
        *(float4*)&C[m * N2_ + nb + tx * 4]      = v0;
        *(float4*)&C[m * N2_ + nb + 64 + tx * 4] = v1;
    }
}

// ---------------------------------------------------------------------------
// Stage 2: tt = relu(Wt1[k] @ h[b,l,k]), output TRANSPOSED to n-major [z][n][o]
// ---------------------------------------------------------------------------
__global__ __launch_bounds__(256) void k_gemm2(const float* __restrict__ Wt1)
{
    const int z = blockIdx.z;
    const int k = z % 3;
    const float* A  = Wt1 + k * CT_ * CT_;
    const float* Bm = g_h + (size_t)z * CT_ * N2_;
    float* C = g_tt + (size_t)z * N2_ * CT_;
    const int nb = blockIdx.x * 128;

    __shared__ float As[16][132];
    __shared__ float Bs[16][132];

    const int tid = threadIdx.x;
    const int tx = tid & 15;
    const int ty = tid >> 4;

    unsigned long long acc[8][4];
#pragma unroll
    for (int i = 0; i < 8; i++)
#pragma unroll
        for (int j = 0; j < 4; j++) acc[i][j] = 0ull;

    for (int k0 = 0; k0 < CT_; k0 += 16) {
#pragma unroll
        for (int i = 0; i < 8; i++) {
            int e = i * 256 + tid;
            int m = e >> 4, kk = e & 15;
            As[kk][m] = A[m * CT_ + k0 + kk];
        }
#pragma unroll
        for (int i = 0; i < 8; i++) {
            int e = i * 256 + tid;
            int n = e & 127, kk = e >> 7;
            Bs[kk][n] = Bm[(k0 + kk) * N2_ + nb + n];
        }
        __syncthreads();
#pragma unroll
        for (int kk = 0; kk < 16; kk++) MMA_KSTEP(kk)
        __syncthreads();
    }

    // transposed write: C[n][o].  old acc[i][j_old], j_old = 2*jp + h
#pragma unroll
    for (int jp = 0; jp < 4; jp++) {
#pragma unroll
        for (int h = 0; h < 2; h++) {
            int j_old = 2 * jp + h;
            int n = (j_old < 4) ? (tx * 4 + j_old) : (64 + tx * 4 + j_old - 4);
            float* Cp = C + (size_t)(nb + n) * CT_;
            float e[8];
#pragma unroll
            for (int i = 0; i < 8; i++) {
                U2F p; p.u = acc[i][jp];
                e[i] = h ? p.f.y : p.f.x;
            }
            float4 v0 = make_float4(fmaxf(e[0],0.f), fmaxf(e[1],0.f),
                                    fmaxf(e[2],0.f), fmaxf(e[3],0.f));
            float4 v1 = make_float4(fmaxf(e[4],0.f), fmaxf(e[5],0.f),
                                    fmaxf(e[6],0.f), fmaxf(e[7],0.f));
            *(float4*)&Cp[ty * 4]      = v0;
            *(float4*)&Cp[64 + ty * 4] = v1;
        }
    }
}

// ---------------------------------------------------------------------------
// KNN: per (b,t1,n1) find top-3 nearest seeds, store weights + gather offsets
// ---------------------------------------------------------------------------
__global__ __launch_bounds__(256) void k_knn(const float* __restrict__ xyzs,
                                             const float* __restrict__ oxyzs)
{
    const int bt  = blockIdx.y;          // b*9 + (t1-1)
    const int bq  = bt / 9;
    const int t1  = bt % 9 + 1;
    const int n   = blockIdx.x * 256 + threadIdx.x;
    const int tid = threadIdx.x;

    // contributing (t2, k) segments, in t2-ascending order (matches concat)
    int t2s[2], ks[2], nseg = 0;
    if ((t1 & 1) == 0) { t2s[0] = t1 / 2 - 1; ks[0] = 1; nseg = 1; }
    else {
        int p = (t1 - 1) >> 1;
        if (p - 1 >= 0) { t2s[nseg] = p - 1; ks[nseg] = 2; nseg++; }
        if (p <= 3)     { t2s[nseg] = p;     ks[nseg] = 0; nseg++; }
    }

    const float* q = oxyzs + ((size_t)bt * N1_ + n) * 3;
    const float qx = q[0], qy = q[1], qz = q[2];

    __shared__ float sr[3 * 1024];
    float b0 = 3.4e38f, b1 = 3.4e38f, b2 = 3.4e38f;
    int   o0 = 0, o1 = 0, o2 = 0;

    for (int s = 0; s < nseg; s++) {
        const float* sp = xyzs + (size_t)(bq * 4 + t2s[s]) * N2_ * 3;
        const int offbase = ((bq * 4 + t2s[s]) * 3 + ks[s]) * (N2_ * CT_);
        for (int base = 0; base < N2_; base += 1024) {
            __syncthreads();
#pragma unroll
            for (int t = tid; t < 3072; t += 256) sr[t] = sp[base * 3 + t];
            __syncthreads();
            for (int t = 0; t < 1024; t++) {
                float dx = qx - sr[3 * t];
                float dy = qy - sr[3 * t + 1];
                float dz = qz - sr[3 * t + 2];
                float d = dx * dx + dy * dy + dz * dz;
                if (d < b2) {
                    int off = offbase + (base + t) * CT_;
                    if (d < b1) {
                        b2 = b1; o2 = o1;
                        if (d < b0) { b1 = b0; o1 = o0; b0 = d; o0 = off; }
                        else        { b1 = d; o1 = off; }
                    } else { b2 = d; o2 = off; }
                }
            }
        }
    }

    float w0 = 1.f / (b0 + 1e-8f);
    float w1 = 1.f / (b1 + 1e-8f);
    float w2 = 1.f / (b2 + 1e-8f);
    float si = 1.f / (w0 + w1 + w2);
    const int base3 = (bt * N1_ + n) * 3;
    g_w[base3]     = w0 * si;
    g_w[base3 + 1] = w1 * si;
    g_w[base3 + 2] = w2 * si;
    g_off[base3]     = o0;
    g_off[base3 + 1] = o1;
    g_off[base3 + 2] = o2;
}

// ---------------------------------------------------------------------------
// Interp: g_bcat[q][c] = sum_j w_j * tt[off_j + c]   (coalesced 512B gathers)
// ---------------------------------------------------------------------------
__global__ void k_interp()
{
    const int gq = blockIdx.x * 4 + threadIdx.y;   // 0 .. 18*8192-1
    const int c  = threadIdx.x;                    // 0..127
    const int b3 = gq * 3;
    const float w0 = g_w[b3], w1 = g_w[b3 + 1], w2 = g_w[b3 + 2];
    const int   o0 = g_off[b3], o1 = g_off[b3 + 1], o2 = g_off[b3 + 2];
    g_bcat[(size_t)gq * CT_ + c] =
        w0 * g_tt[o0 + c] + w1 * g_tt[o1 + c] + w2 * g_tt[o2 + c];
}

// ---------------------------------------------------------------------------
// Stage 3: out = relu(bn(Ws @ concat(interp, orig_feats)))
//   18 x (256 x 192 x 8192). K<128 from g_bcat (n-major), K>=128 from OF.
// ---------------------------------------------------------------------------
__global__ __launch_bounds__(256) void k_gemm3(
    const float* __restrict__ Ws, const float* __restrict__ OF,
    const float* __restrict__ gamma, const float* __restrict__ beta,
    const float* __restrict__ mean,  const float* __restrict__ var,
    float* __restrict__ out)
{
    const int bt = blockIdx.z;           // 0..17
    const int m0 = blockIdx.y * 128;     // 0 or 128
    const int nb = blockIdx.x * 128;
    const float* A  = Ws + m0 * KD3_;
    const float* Bt = g_bcat + (size_t)bt * N1_ * CT_;

    __shared__ float As[16][132];
    __shared__ float Bs[16][132];

    const int tid = threadIdx.x;
    const int tx = tid & 15;
    const int ty = tid >> 4;

    unsigned long long acc[8][4];
#pragma unroll
    for (int i = 0; i < 8; i++)
#pragma unroll
        for (int j = 0; j < 4; j++) acc[i][j] = 0ull;

    for (int k0 = 0; k0 < KD3_; k0 += 16) {
#pragma unroll
        for (int i = 0; i < 8; i++) {
            int e = i * 256 + tid;
            int m = e >> 4, kk = e & 15;
            As[kk][m] = A[m * KD3_ + k0 + kk];
        }
        if (k0 < CT_) {
            // interp part, n-major: Bt[n][c]
#pragma unroll
            for (int i = 0; i < 8; i++) {
                int e = i * 256 + tid;
                int kk = e & 15, n = e >> 4;
                Bs[kk][n] = Bt[(size_t)(nb + n) * CT_ + k0 + kk];
            }
        } else {
            // original_features part, c-major: OF[(bt*64 + c)*N1 + n]
            const float* OFp = OF + ((size_t)bt * CORIG_ + (k0 - CT_)) * N1_ + nb;
#pragma unroll
            for (int i = 0; i < 8; i++) {
                int e = i * 256 + tid;
                int n = e & 127, kk = e >> 7;
                Bs[kk][n] = OFp[(size_t)kk * N1_ + n];
            }
        }
        __syncthreads();
#pragma unroll
        for (int kk = 0; kk < 16; kk++) MMA_KSTEP(kk)
        __syncthreads();
    }

#pragma unroll
    for (int i = 0; i < 8; i++) {
        int m = m0 + ((i < 4) ? (ty * 4 + i) : (64 + ty * 4 + i - 4));
        float sc = gamma[m] * rsqrtf(var[m] + 1e-5f);
        float bi = beta[m] - mean[m] * sc;
        float* Cp = out + ((size_t)bt * CS_ + m) * N1_ + nb;
        U2F p0, p1, p2, p3;
        p0.u = acc[i][0]; p1.u = acc[i][1]; p2.u = acc[i][2]; p3.u = acc[i][3];
        float4 v0 = make_float4(fmaxf(p0.f.x*sc+bi,0.f), fmaxf(p0.f.y*sc+bi,0.f),
                                fmaxf(p1.f.x*sc+bi,0.f), fmaxf(p1.f.y*sc+bi,0.f));
        float4 v1 = make_float4(fmaxf(p2.f.x*sc+bi,0.f), fmaxf(p2.f.y*sc+bi,0.f),
                                fmaxf(p3.f.x*sc+bi,0.f), fmaxf(p3.f.y*sc+bi,0.f));
        *(float4*)&Cp[tx * 4]      = v0;
        *(float4*)&Cp[64 + tx * 4] = v1;
    }
}

// ---------------------------------------------------------------------------
extern "C" void kernel_launch(void* const* d_in, const int* in_sizes, int n_in,
                              void* d_out, int out_size)
{
    const float* xyzs   = (const float*)d_in[0];
    const float* oxyzs  = (const float*)d_in[1];
    const float* feats  = (const float*)d_in[2];
    const float* ofeats = (const float*)d_in[3];
    const float* Wt0    = (const float*)d_in[4];
    const float* Wt1    = (const float*)d_in[5];
    const float* Ws     = (const float*)d_in[6];
    const float* gamma  = (const float*)d_in[7];
    const float* beta   = (const float*)d_in[8];
    const float* mean   = (const float*)d_in[9];
    const float* var    = (const float*)d_in[10];

    const int NEWF = B_ * L1_ * CS_ * N1_;   // 37,748,736
    int ofs = out_size - NEWF;               // expect 442,368 (original_xyzs) or 0
    float* outF = (float*)d_out;
    if (ofs > 0) {
        cudaMemcpyAsync(d_out, d_in[1], (size_t)ofs * sizeof(float),
                        cudaMemcpyDeviceToDevice, 0);
        outF += ofs;
    }

    k_gemm1<<<dim3(16, 1, 24), 256>>>(Wt0, feats);
    k_gemm2<<<dim3(16, 1, 24), 256>>>(Wt1);
    k_knn<<<dim3(32, 18), 256>>>(xyzs, oxyzs);
    k_interp<<<B_ * L1_ * N1_ / 4, dim3(128, 4)>>>();
    k_gemm3<<<dim3(64, 2, 18), 256>>>(Ws, ofeats, gamma, beta, mean, var, outF);
}

// round 4
// speedup vs baseline: 1.2727x; 1.1726x over previous
#include <cuda_runtime.h>
#include <cuda_bf16.h>
#include <cstdint>

// Problem constants
#define B_     2
#define L2_    4
#define N2_    2048
#define L1_    9
#define N1_    8192
#define CIN_   128
#define CT_    128
#define CS_    256
#define CORIG_ 64
#define KD3_   192   // CT_ + CORIG_

// Scratch (static device globals — no runtime allocation)
__device__ float g_h  [B_*L2_*3*CT_*N2_];            // stage-1 out [z][o][n]
__device__ float g_tt [B_*L2_*3*N2_*CT_];            // stage-2 out, n-major [z][n][o]
__device__ int   g_off[B_*L1_*N1_*3];
__device__ float g_w  [B_*L1_*N1_*3];
__device__ __align__(128) __nv_bfloat16 g_bhi[(size_t)B_*L1_*N1_*KD3_];
__device__ __align__(128) __nv_bfloat16 g_blo[(size_t)B_*L1_*N1_*KD3_];
__device__ __align__(128) __nv_bfloat16 g_whi[CS_*KD3_];
__device__ __align__(128) __nv_bfloat16 g_wlo[CS_*KD3_];

__device__ __forceinline__ uint32_t smem_u32(const void* p) {
    uint32_t a;
    asm("{ .reg .u64 t; cvta.to.shared.u64 t, %1; cvt.u32.u64 %0, t; }"
        : "=r"(a) : "l"(p));
    return a;
}
__device__ __forceinline__ void ldmx4(uint32_t* r, uint32_t addr) {
    asm volatile("ldmatrix.sync.aligned.m8n8.x4.shared.b16 {%0,%1,%2,%3}, [%4];"
                 : "=r"(r[0]), "=r"(r[1]), "=r"(r[2]), "=r"(r[3]) : "r"(addr));
}
__device__ __forceinline__ void mma_bf16(float* d, const uint32_t* a,
                                         const uint32_t* b) {
    asm volatile("mma.sync.aligned.m16n8k16.row.col.f32.bf16.bf16.f32 "
                 "{%0,%1,%2,%3}, {%4,%5,%6,%7}, {%8,%9}, {%0,%1,%2,%3};"
                 : "+f"(d[0]), "+f"(d[1]), "+f"(d[2]), "+f"(d[3])
                 : "r"(a[0]), "r"(a[1]), "r"(a[2]), "r"(a[3]),
                   "r"(b[0]), "r"(b[1]));
}

// ---- packed f32x2 helpers ------------------------------------------------
__device__ __forceinline__ unsigned long long dup2(float x) {
    unsigned long long r;
    asm("mov.b64 %0, {%1, %1};" : "=l"(r) : "f"(x));
    return r;
}
__device__ __forceinline__ void ffma2(unsigned long long& d,
                                      unsigned long long a,
                                      unsigned long long b) {
    asm("fma.rn.f32x2 %0, %1, %2, %0;" : "+l"(d) : "l"(a), "l"(b));
}
union F4U { float4 f4; unsigned long long u[2]; };
union U2F { unsigned long long u; float2 f; };

#define MMA_KSTEP(kk)                                                        \
    {                                                                        \
        float4 a0 = *(const float4*)&As[kk][ty * 4];                         \
        float4 a1 = *(const float4*)&As[kk][64 + ty * 4];                    \
        F4U b0, b1;                                                          \
        b0.f4 = *(const float4*)&Bs[kk][tx * 4];                             \
        b1.f4 = *(const float4*)&Bs[kk][64 + tx * 4];                        \
        unsigned long long ad[8] = {dup2(a0.x), dup2(a0.y), dup2(a0.z),      \
                                    dup2(a0.w), dup2(a1.x), dup2(a1.y),      \
                                    dup2(a1.z), dup2(a1.w)};                 \
        unsigned long long bd[4] = {b0.u[0], b0.u[1], b1.u[0], b1.u[1]};     \
        _Pragma("unroll")                                                    \
        for (int i = 0; i < 8; i++) {                                        \
            _Pragma("unroll")                                                \
            for (int j = 0; j < 4; j++) ffma2(acc[i][j], ad[i], bd[j]);      \
        }                                                                    \
    }

// ---------------------------------------------------------------------------
// Stage 1: h = relu(Wt0[k] @ features[b,l]),  24 x (128x128x2048)
// ---------------------------------------------------------------------------
__global__ __launch_bounds__(256) void k_gemm1(const float* __restrict__ Wt0,
                                               const float* __restrict__ F)
{
    const int z  = blockIdx.z;
    const int k  = z % 3;
    const int bl = z / 3;
    const float* A  = Wt0 + k  * CT_ * CIN_;
    const float* Bm = F   + bl * CIN_ * N2_;
    float* C = g_h + (size_t)z * CT_ * N2_;
    const int nb = blockIdx.x * 128;

    __shared__ float As[16][132];
    __shared__ float Bs[16][132];
    const int tid = threadIdx.x, tx = tid & 15, ty = tid >> 4;

    unsigned long long acc[8][4];
#pragma unroll
    for (int i = 0; i < 8; i++)
#pragma unroll
        for (int j = 0; j < 4; j++) acc[i][j] = 0ull;

    for (int k0 = 0; k0 < CIN_; k0 += 16) {
#pragma unroll
        for (int i = 0; i < 8; i++) {
            int e = i * 256 + tid, m = e >> 4, kk = e & 15;
            As[kk][m] = A[m * CIN_ + k0 + kk];
        }
#pragma unroll
        for (int i = 0; i < 8; i++) {
            int e = i * 256 + tid, n = e & 127, kk = e >> 7;
            Bs[kk][n] = Bm[(k0 + kk) * N2_ + nb + n];
        }
        __syncthreads();
#pragma unroll
        for (int kk = 0; kk < 16; kk++) MMA_KSTEP(kk)
        __syncthreads();
    }
#pragma unroll
    for (int i = 0; i < 8; i++) {
        int m = (i < 4) ? (ty * 4 + i) : (64 + ty * 4 + i - 4);
        U2F p0, p1, p2, p3;
        p0.u = acc[i][0]; p1.u = acc[i][1]; p2.u = acc[i][2]; p3.u = acc[i][3];
        float4 v0 = make_float4(fmaxf(p0.f.x,0.f), fmaxf(p0.f.y,0.f),
                                fmaxf(p1.f.x,0.f), fmaxf(p1.f.y,0.f));
        float4 v1 = make_float4(fmaxf(p2.f.x,0.f), fmaxf(p2.f.y,0.f),
                                fmaxf(p3.f.x,0.f), fmaxf(p3.f.y,0.f));
        *(float4*)&C[m * N2_ + nb + tx * 4]      = v0;
        *(float4*)&C[m * N2_ + nb + 64 + tx * 4] = v1;
    }
}

// ---------------------------------------------------------------------------
// Stage 2: tt = relu(Wt1[k] @ h), output transposed n-major [z][n][o]
// ---------------------------------------------------------------------------
__global__ __launch_bounds__(256) void k_gemm2(const float* __restrict__ Wt1)
{
    const int z = blockIdx.z;
    const int k = z % 3;
    const float* A  = Wt1 + k * CT_ * CT_;
    const float* Bm = g_h + (size_t)z * CT_ * N2_;
    float* C = g_tt + (size_t)z * N2_ * CT_;
    const int nb = blockIdx.x * 128;

    __shared__ float As[16][132];
    __shared__ float Bs[16][132];
    const int tid = threadIdx.x, tx = tid & 15, ty = tid >> 4;

    unsigned long long acc[8][4];
#pragma unroll
    for (int i = 0; i < 8; i++)
#pragma unroll
        for (int j = 0; j < 4; j++) acc[i][j] = 0ull;

    for (int k0 = 0; k0 < CT_; k0 += 16) {
#pragma unroll
        for (int i = 0; i < 8; i++) {
            int e = i * 256 + tid, m = e >> 4, kk = e & 15;
            As[kk][m] = A[m * CT_ + k0 + kk];
        }
#pragma unroll
        for (int i = 0; i < 8; i++) {
            int e = i * 256 + tid, n = e & 127, kk = e >> 7;
            Bs[kk][n] = Bm[(k0 + kk) * N2_ + nb + n];
        }
        __syncthreads();
#pragma unroll
        for (int kk = 0; kk < 16; kk++) MMA_KSTEP(kk)
        __syncthreads();
    }
#pragma unroll
    for (int jp = 0; jp < 4; jp++) {
#pragma unroll
        for (int h = 0; h < 2; h++) {
            int j_old = 2 * jp + h;
            int n = (j_old < 4) ? (tx * 4 + j_old) : (64 + tx * 4 + j_old - 4);
            float* Cp = C + (size_t)(nb + n) * CT_;
            float e[8];
#pragma unroll
            for (int i = 0; i < 8; i++) {
                U2F p; p.u = acc[i][jp];
                e[i] = h ? p.f.y : p.f.x;
            }
            float4 v0 = make_float4(fmaxf(e[0],0.f), fmaxf(e[1],0.f),
                                    fmaxf(e[2],0.f), fmaxf(e[3],0.f));
            float4 v1 = make_float4(fmaxf(e[4],0.f), fmaxf(e[5],0.f),
                                    fmaxf(e[6],0.f), fmaxf(e[7],0.f));
            *(float4*)&Cp[ty * 4]      = v0;
            *(float4*)&Cp[64 + ty * 4] = v1;
        }
    }
}

// ---------------------------------------------------------------------------
// KNN
// ---------------------------------------------------------------------------
__global__ __launch_bounds__(256) void k_knn(const float* __restrict__ xyzs,
                                             const float* __restrict__ oxyzs)
{
    const int bt  = blockIdx.y;
    const int bq  = bt / 9;
    const int t1  = bt % 9 + 1;
    const int n   = blockIdx.x * 256 + threadIdx.x;
    const int tid = threadIdx.x;

    int t2s[2], ks[2], nseg = 0;
    if ((t1 & 1) == 0) { t2s[0] = t1 / 2 - 1; ks[0] = 1; nseg = 1; }
    else {
        int p = (t1 - 1) >> 1;
        if (p - 1 >= 0) { t2s[nseg] = p - 1; ks[nseg] = 2; nseg++; }
        if (p <= 3)     { t2s[nseg] = p;     ks[nseg] = 0; nseg++; }
    }

    const float* q = oxyzs + ((size_t)bt * N1_ + n) * 3;
    const float qx = q[0], qy = q[1], qz = q[2];

    __shared__ float sr[3 * 1024];
    float b0 = 3.4e38f, b1 = 3.4e38f, b2 = 3.4e38f;
    int   o0 = 0, o1 = 0, o2 = 0;

    for (int s = 0; s < nseg; s++) {
        const float* sp = xyzs + (size_t)(bq * 4 + t2s[s]) * N2_ * 3;
        const int offbase = ((bq * 4 + t2s[s]) * 3 + ks[s]) * (N2_ * CT_);
        for (int base = 0; base < N2_; base += 1024) {
            __syncthreads();
#pragma unroll
            for (int t = tid; t < 3072; t += 256) sr[t] = sp[base * 3 + t];
            __syncthreads();
            for (int t = 0; t < 1024; t++) {
                float dx = qx - sr[3 * t];
                float dy = qy - sr[3 * t + 1];
                float dz = qz - sr[3 * t + 2];
                float d = dx * dx + dy * dy + dz * dz;
                if (d < b2) {
                    int off = offbase + (base + t) * CT_;
                    if (d < b1) {
                        b2 = b1; o2 = o1;
                        if (d < b0) { b1 = b0; o1 = o0; b0 = d; o0 = off; }
                        else        { b1 = d; o1 = off; }
                    } else { b2 = d; o2 = off; }
                }
            }
        }
    }

    float w0 = 1.f / (b0 + 1e-8f);
    float w1 = 1.f / (b1 + 1e-8f);
    float w2 = 1.f / (b2 + 1e-8f);
    float si = 1.f / (w0 + w1 + w2);
    const int base3 = (bt * N1_ + n) * 3;
    g_w[base3]     = w0 * si;
    g_w[base3 + 1] = w1 * si;
    g_w[base3 + 2] = w2 * si;
    g_off[base3]     = o0;
    g_off[base3 + 1] = o1;
    g_off[base3 + 2] = o2;
}

// ---------------------------------------------------------------------------
// Interp → writes hi/lo bf16 rows [q][0..127] of the B operand
// ---------------------------------------------------------------------------
__global__ void k_interp()
{
    const int gq = blockIdx.x * 4 + threadIdx.y;
    const int c  = threadIdx.x;
    const int b3 = gq * 3;
    const float w0 = g_w[b3], w1 = g_w[b3 + 1], w2 = g_w[b3 + 2];
    const int   o0 = g_off[b3], o1 = g_off[b3 + 1], o2 = g_off[b3 + 2];
    float v = w0 * g_tt[o0 + c] + w1 * g_tt[o1 + c] + w2 * g_tt[o2 + c];
    __nv_bfloat16 hi = __float2bfloat16(v);
    __nv_bfloat16 lo = __float2bfloat16(v - __bfloat162float(hi));
    size_t d = (size_t)gq * KD3_ + c;
    g_bhi[d] = hi;
    g_blo[d] = lo;
}

// ---------------------------------------------------------------------------
// OF transpose+convert: OF[bt][c][n] -> g_bhi/lo[(bt*N1+n)*192 + 128 + c]
// ---------------------------------------------------------------------------
__global__ __launch_bounds__(256) void k_oftrans(const float* __restrict__ OF)
{
    const int bt = blockIdx.y;
    const int nb = blockIdx.x * 64;
    __shared__ __nv_bfloat16 sh[64][65], sl[64][65];
    const int tid = threadIdx.x;
#pragma unroll
    for (int i = 0; i < 16; i++) {
        int idx = tid + i * 256;
        int c = idx >> 6, n = idx & 63;
        float v = OF[((size_t)bt * CORIG_ + c) * N1_ + nb + n];
        __nv_bfloat16 hi = __float2bfloat16(v);
        sh[c][n] = hi;
        sl[c][n] = __float2bfloat16(v - __bfloat162float(hi));
    }
    __syncthreads();
#pragma unroll
    for (int i = 0; i < 16; i++) {
        int idx = tid + i * 256;
        int n = idx >> 6, c = idx & 63;
        size_t d = ((size_t)bt * N1_ + nb + n) * KD3_ + CT_ + c;
        g_bhi[d] = sh[c][n];
        g_blo[d] = sl[c][n];
    }
}

// ---------------------------------------------------------------------------
// Ws convert
// ---------------------------------------------------------------------------
__global__ void k_wsconv(const float* __restrict__ Ws)
{
    int i = blockIdx.x * 256 + threadIdx.x;   // 192 x 256 = 49152
    float v = Ws[i];
    __nv_bfloat16 hi = __float2bfloat16(v);
    g_whi[i] = hi;
    g_wlo[i] = __float2bfloat16(v - __bfloat162float(hi));
}

// ---------------------------------------------------------------------------
// Stage 3 via mma.sync bf16 split-3:
//   D = Whi*Bhi + Whi*Blo + Wlo*Bhi over K'=576 (9 chunks of 64)
// CTA: 256(M) x 128(N), 512 threads, 16 warps (8m x 2n), warp tile 32x64.
// smem: A 256x64 bf16 (32KB) + B 128x64 bf16 (16KB), XOR-16B swizzled rows.
// ---------------------------------------------------------------------------
__global__ __launch_bounds__(512, 1) void k_mma3(
    const float* __restrict__ gamma, const float* __restrict__ beta,
    const float* __restrict__ mean,  const float* __restrict__ var,
    float* __restrict__ out)
{
    __shared__ __align__(128) char sA[256 * 128];
    __shared__ __align__(128) char sB[128 * 128];

    const int tid  = threadIdx.x;
    const int wid  = tid >> 5, lane = tid & 31;
    const int bt   = blockIdx.z;
    const int nb   = blockIdx.x * 128;
    const int m_w  = (wid & 7) * 32;
    const int n_w  = (wid >> 3) * 64;

    const uint32_t sa_b = smem_u32(sA);
    const uint32_t sb_b = smem_u32(sB);
    const size_t   brow = ((size_t)bt * N1_ + nb) * KD3_;

    float d[2][8][4];
#pragma unroll
    for (int mt = 0; mt < 2; mt++)
#pragma unroll
        for (int nt = 0; nt < 8; nt++)
#pragma unroll
            for (int r = 0; r < 4; r++) d[mt][nt][r] = 0.f;

    for (int chunk = 0; chunk < 9; chunk++) {
        const int p  = chunk / 3;
        const int k0 = (chunk % 3) * 64;
        const __nv_bfloat16* Asrc = (p < 2) ? g_whi : g_wlo;
        const __nv_bfloat16* Bsrc = (p == 1) ? g_blo : g_bhi;
        __syncthreads();
#pragma unroll
        for (int i = 0; i < 4; i++) {           // A: 2048 uint4
            int idx = tid + i * 512;
            int m = idx >> 3, part = idx & 7;
            uint4 v = *(const uint4*)(Asrc + m * KD3_ + k0 + part * 8);
            *(uint4*)(sA + m * 128 + ((part * 16) ^ ((m & 7) << 4))) = v;
        }
#pragma unroll
        for (int i = 0; i < 2; i++) {           // B: 1024 uint4
            int idx = tid + i * 512;
            int n = idx >> 3, part = idx & 7;
            uint4 v = *(const uint4*)(Bsrc + brow + (size_t)n * KD3_ + k0 + part * 8);
            *(uint4*)(sB + n * 128 + ((part * 16) ^ ((n & 7) << 4))) = v;
        }
        __syncthreads();

#pragma unroll
        for (int ks = 0; ks < 4; ks++) {
            uint32_t a[2][4];
#pragma unroll
            for (int mt = 0; mt < 2; mt++) {
                int m = m_w + mt * 16 + (lane & 15);
                uint32_t addr = sa_b + m * 128 +
                    (((uint32_t)(ks * 32 + (lane >> 4) * 16)) ^ ((m & 7) << 4));
                ldmx4(a[mt], addr);
            }
            uint32_t b[4][4];
#pragma unroll
            for (int pr = 0; pr < 4; pr++) {
                int n = n_w + pr * 16 + (lane >> 4) * 8 + (lane & 7);
                uint32_t addr = sb_b + n * 128 +
                    (((uint32_t)(ks * 32 + ((lane >> 3) & 1) * 16)) ^ ((n & 7) << 4));
                ldmx4(b[pr], addr);
            }
#pragma unroll
            for (int mt = 0; mt < 2; mt++)
#pragma unroll
                for (int nt = 0; nt < 8; nt++)
                    mma_bf16(d[mt][nt], a[mt], &b[nt >> 1][(nt & 1) * 2]);
        }
    }

    // epilogue: BN + relu, scattered per mma layout (sector-coalesced float2)
    const int qrow = lane >> 2, qcol = (lane & 3) * 2;
#pragma unroll
    for (int mt = 0; mt < 2; mt++) {
#pragma unroll
        for (int half = 0; half < 2; half++) {
            int m = m_w + mt * 16 + half * 8 + qrow;
            float sc = gamma[m] * rsqrtf(var[m] + 1e-5f);
            float bi = beta[m] - mean[m] * sc;
            float* Cp = out + ((size_t)bt * CS_ + m) * N1_ + nb + n_w;
#pragma unroll
            for (int nt = 0; nt < 8; nt++) {
                float x = fmaxf(d[mt][nt][half * 2]     * sc + bi, 0.f);
                float y = fmaxf(d[mt][nt][half * 2 + 1] * sc + bi, 0.f);
                *(float2*)&Cp[nt * 8 + qcol] = make_float2(x, y);
            }
        }
    }
}

// ---------------------------------------------------------------------------
extern "C" void kernel_launch(void* const* d_in, const int* in_sizes, int n_in,
                              void* d_out, int out_size)
{
    const float* xyzs   = (const float*)d_in[0];
    const float* oxyzs  = (const float*)d_in[1];
    const float* feats  = (const float*)d_in[2];
    const float* ofeats = (const float*)d_in[3];
    const float* Wt0    = (const float*)d_in[4];
    const float* Wt1    = (const float*)d_in[5];
    const float* Ws     = (const float*)d_in[6];
    const float* gamma  = (const float*)d_in[7];
    const float* beta   = (const float*)d_in[8];
    const float* mean   = (const float*)d_in[9];
    const float* var    = (const float*)d_in[10];

    const int NEWF = B_ * L1_ * CS_ * N1_;
    int ofs = out_size - NEWF;
    float* outF = (float*)d_out;
    if (ofs > 0) {
        cudaMemcpyAsync(d_out, d_in[1], (size_t)ofs * sizeof(float),
                        cudaMemcpyDeviceToDevice, 0);
        outF += ofs;
    }

    k_wsconv<<<192, 256>>>(Ws);
    k_gemm1<<<dim3(16, 1, 24), 256>>>(Wt0, feats);
    k_gemm2<<<dim3(16, 1, 24), 256>>>(Wt1);
    k_oftrans<<<dim3(128, 18), 256>>>(ofeats);
    k_knn<<<dim3(32, 18), 256>>>(xyzs, oxyzs);
    k_interp<<<B_ * L1_ * N1_ / 4, dim3(128, 4)>>>();
    k_mma3<<<dim3(64, 1, 18), 512>>>(gamma, beta, mean, var, outF);
}

// round 5
// speedup vs baseline: 1.4069x; 1.1055x over previous
#include <cuda_runtime.h>
#include <cuda_bf16.h>
#include <cstdint>

// Problem constants
#define B_     2
#define L2_    4
#define N2_    2048
#define L1_    9
#define N1_    8192
#define CIN_   128
#define CT_    128
#define CS_    256
#define CORIG_ 64
#define KD3_   192   // CT_ + CORIG_

typedef __nv_bfloat16 bf16;

// Scratch (static device globals — no runtime allocation)
__device__ float g_tt [B_*L2_*3*N2_*CT_];                 // stage-2 out, n-major [z][n][o] fp32
__device__ __align__(128) bf16 g_wt0h[3*CT_*CIN_];
__device__ __align__(128) bf16 g_wt0l[3*CT_*CIN_];
__device__ __align__(128) bf16 g_wt1h[3*CT_*CT_];
__device__ __align__(128) bf16 g_wt1l[3*CT_*CT_];
__device__ __align__(128) bf16 g_whi [CS_*KD3_];
__device__ __align__(128) bf16 g_wlo [CS_*KD3_];
__device__ __align__(128) bf16 g_fh  [(size_t)B_*L2_*CIN_*N2_];
__device__ __align__(128) bf16 g_fl  [(size_t)B_*L2_*CIN_*N2_];
__device__ __align__(128) bf16 g_hh  [(size_t)B_*L2_*3*CT_*N2_];
__device__ __align__(128) bf16 g_hl  [(size_t)B_*L2_*3*CT_*N2_];
__device__ __align__(128) bf16 g_bhi [(size_t)B_*L1_*N1_*KD3_];
__device__ __align__(128) bf16 g_blo [(size_t)B_*L1_*N1_*KD3_];

__device__ __forceinline__ uint32_t smem_u32(const void* p) {
    uint32_t a;
    asm("{ .reg .u64 t; cvta.to.shared.u64 t, %1; cvt.u32.u64 %0, t; }"
        : "=r"(a) : "l"(p));
    return a;
}
__device__ __forceinline__ void ldmx4(uint32_t* r, uint32_t addr) {
    asm volatile("ldmatrix.sync.aligned.m8n8.x4.shared.b16 {%0,%1,%2,%3}, [%4];"
                 : "=r"(r[0]), "=r"(r[1]), "=r"(r[2]), "=r"(r[3]) : "r"(addr));
}
__device__ __forceinline__ void ldmx4t(uint32_t* r, uint32_t addr) {
    asm volatile("ldmatrix.sync.aligned.m8n8.x4.trans.shared.b16 {%0,%1,%2,%3}, [%4];"
                 : "=r"(r[0]), "=r"(r[1]), "=r"(r[2]), "=r"(r[3]) : "r"(addr));
}
__device__ __forceinline__ void mma_bf16(float* d, const uint32_t* a,
                                         const uint32_t* b) {
    asm volatile("mma.sync.aligned.m16n8k16.row.col.f32.bf16.bf16.f32 "
                 "{%0,%1,%2,%3}, {%4,%5,%6,%7}, {%8,%9}, {%0,%1,%2,%3};"
                 : "+f"(d[0]), "+f"(d[1]), "+f"(d[2]), "+f"(d[3])
                 : "r"(a[0]), "r"(a[1]), "r"(a[2]), "r"(a[3]),
                   "r"(b[0]), "r"(b[1]));
}
__device__ __forceinline__ void split_bf16(float v, bf16& hi, bf16& lo) {
    hi = __float2bfloat16(v);
    lo = __float2bfloat16(v - __bfloat162float(hi));
}

// ---------------------------------------------------------------------------
// Prep (one kernel): weight splits, feature split, OF transpose+split
//   blocks [0,576): Wt0|Wt1|Ws elementwise split
//   blocks [576,8768): features split (identical layout copy)
//   blocks [8768,11072): OF transpose into g_bhi/g_blo cols 128..191
// ---------------------------------------------------------------------------
#define PREP_W   576
#define PREP_F   8192
#define PREP_OF  2304
__global__ __launch_bounds__(256) void k_prep(
    const float* __restrict__ Wt0, const float* __restrict__ Wt1,
    const float* __restrict__ Ws,  const float* __restrict__ F,
    const float* __restrict__ OF)
{
    const int bx  = blockIdx.x;
    const int tid = threadIdx.x;
    if (bx < PREP_W) {
        int i = bx * 256 + tid;   // 0..147455
        bf16 hi, lo;
        if (i < 49152) {
            split_bf16(Wt0[i], hi, lo);
            g_wt0h[i] = hi; g_wt0l[i] = lo;
        } else if (i < 98304) {
            int j = i - 49152;
            split_bf16(Wt1[j], hi, lo);
            g_wt1h[j] = hi; g_wt1l[j] = lo;
        } else {
            int j = i - 98304;
            split_bf16(Ws[j], hi, lo);
            g_whi[j] = hi; g_wlo[j] = lo;
        }
    } else if (bx < PREP_W + PREP_F) {
        size_t i = (size_t)(bx - PREP_W) * 256 + tid;
        bf16 hi, lo;
        split_bf16(F[i], hi, lo);
        g_fh[i] = hi; g_fl[i] = lo;
    } else {
        const int rb = bx - PREP_W - PREP_F;
        const int bt = rb >> 7;
        const int nb = (rb & 127) * 64;
        __shared__ bf16 sh[64][65], sl[64][65];
#pragma unroll
        for (int i = 0; i < 16; i++) {
            int idx = tid + i * 256;
            int c = idx >> 6, n = idx & 63;
            bf16 hi, lo;
            split_bf16(OF[((size_t)bt * CORIG_ + c) * N1_ + nb + n], hi, lo);
            sh[c][n] = hi; sl[c][n] = lo;
        }
        __syncthreads();
#pragma unroll
        for (int i = 0; i < 16; i++) {
            int idx = tid + i * 256;
            int n = idx >> 6, c = idx & 63;
            size_t d = ((size_t)bt * N1_ + nb + n) * KD3_ + CT_ + c;
            g_bhi[d] = sh[c][n];
            g_blo[d] = sl[c][n];
        }
    }
}

// ---------------------------------------------------------------------------
// HMMA GEMM for stages 1 & 2 (split-3 bf16):
//   C[128m x 128n] = A[128m x 128k] @ B[128k x 128n] per z, 3 passes.
// A row-major k-contiguous (weights), B [k][n] n-contiguous (ldmatrix.trans).
// CTA 128x128, 256 thr, 8 warps (4m x 2n), warp 32x64.
// STAGE 1: A=Wt0 split, B=features split, epi -> g_hh/g_hl (relu, split bf16)
// STAGE 2: A=Wt1 split, B=g_hh/g_hl,     epi -> g_tt fp32 transposed [n][o]
// ---------------------------------------------------------------------------
template<int STAGE>
__global__ __launch_bounds__(256) void k_hgemm()
{
    __shared__ __align__(128) char sA[128 * 128];   // 128m x 64k bf16
    __shared__ __align__(128) char sB[64 * 256];    // 64k x 128n bf16

    const int tid  = threadIdx.x;
    const int wid  = tid >> 5, lane = tid & 31;
    const int z    = blockIdx.z;          // (b*4+l)*3 + kker
    const int nb   = blockIdx.x * 128;
    const int m_w  = (wid & 3) * 32;
    const int n_w  = (wid >> 2) * 64;

    const bf16* Ah;
    const bf16* Al;
    const bf16* Bh;
    const bf16* Bl;
    if (STAGE == 1) {
        Ah = g_wt0h + (z % 3) * CT_ * CIN_;
        Al = g_wt0l + (z % 3) * CT_ * CIN_;
        Bh = g_fh + (size_t)(z / 3) * CIN_ * N2_;
        Bl = g_fl + (size_t)(z / 3) * CIN_ * N2_;
    } else {
        Ah = g_wt1h + (z % 3) * CT_ * CT_;
        Al = g_wt1l + (z % 3) * CT_ * CT_;
        Bh = g_hh + (size_t)z * CT_ * N2_;
        Bl = g_hl + (size_t)z * CT_ * N2_;
    }

    const uint32_t sa_b = smem_u32(sA);
    const uint32_t sb_b = smem_u32(sB);

    float d[2][8][4];
#pragma unroll
    for (int mt = 0; mt < 2; mt++)
#pragma unroll
        for (int nt = 0; nt < 8; nt++)
#pragma unroll
            for (int r = 0; r < 4; r++) d[mt][nt][r] = 0.f;

    for (int chunk = 0; chunk < 6; chunk++) {
        const int p  = chunk >> 1;
        const int k0 = (chunk & 1) * 64;
        const bf16* Asrc = (p < 2) ? Ah : Al;
        const bf16* Bsrc = (p == 1) ? Bl : Bh;
        __syncthreads();
        // A: 128 rows x 64k = 1024 uint4
#pragma unroll
        for (int i = 0; i < 4; i++) {
            int idx = tid + i * 256;
            int m = idx >> 3, u = idx & 7;
            uint4 v = *(const uint4*)(Asrc + m * 128 + k0 + u * 8);
            *(uint4*)(sA + m * 128 + ((u * 16) ^ ((m & 7) << 4))) = v;
        }
        // B: 64 k-rows x 128n = 1024 uint4 (rows 256B)
#pragma unroll
        for (int i = 0; i < 4; i++) {
            int idx = tid + i * 256;
            int kr = idx >> 4, u = idx & 15;
            uint4 v = *(const uint4*)(Bsrc + (size_t)(k0 + kr) * N2_ + nb + u * 8);
            *(uint4*)(sB + kr * 256 + ((u * 16) ^ ((kr & 7) << 4))) = v;
        }
        __syncthreads();

#pragma unroll
        for (int ks = 0; ks < 4; ks++) {
            uint32_t a[2][4];
#pragma unroll
            for (int mt = 0; mt < 2; mt++) {
                int m = m_w + mt * 16 + (lane & 15);
                uint32_t addr = sa_b + m * 128 +
                    (((uint32_t)(ks * 32 + (lane >> 4) * 16)) ^ ((m & 7) << 4));
                ldmx4(a[mt], addr);
            }
            uint32_t b[4][4];
#pragma unroll
            for (int pr = 0; pr < 4; pr++) {
                int kr = ks * 16 + (lane & 15);
                uint32_t nc = (uint32_t)(n_w + pr * 16 + (lane >> 4) * 8) * 2;
                uint32_t addr = sb_b + kr * 256 + (nc ^ ((kr & 7) << 4));
                ldmx4t(b[pr], addr);
            }
#pragma unroll
            for (int mt = 0; mt < 2; mt++)
#pragma unroll
                for (int nt = 0; nt < 8; nt++)
                    mma_bf16(d[mt][nt], a[mt], &b[nt >> 1][(nt & 1) * 2]);
        }
    }

    const int qrow = lane >> 2, qcol = (lane & 3) * 2;
    if (STAGE == 1) {
        // h = relu(acc) -> split bf16, layout [z][m][n]
        bf16* Hh = g_hh + (size_t)z * CT_ * N2_;
        bf16* Hl = g_hl + (size_t)z * CT_ * N2_;
#pragma unroll
        for (int mt = 0; mt < 2; mt++) {
#pragma unroll
            for (int half = 0; half < 2; half++) {
                int row = m_w + mt * 16 + half * 8 + qrow;
#pragma unroll
                for (int nt = 0; nt < 8; nt++) {
                    int col = nb + n_w + nt * 8 + qcol;
                    float x = fmaxf(d[mt][nt][half * 2],     0.f);
                    float y = fmaxf(d[mt][nt][half * 2 + 1], 0.f);
                    bf16 xh, xl, yh, yl;
                    split_bf16(x, xh, xl);
                    split_bf16(y, yh, yl);
                    __nv_bfloat162 vh; vh.x = xh; vh.y = yh;
                    __nv_bfloat162 vl; vl.x = xl; vl.y = yl;
                    *(__nv_bfloat162*)(Hh + (size_t)row * N2_ + col) = vh;
                    *(__nv_bfloat162*)(Hl + (size_t)row * N2_ + col) = vl;
                }
            }
        }
    } else {
        // tt = relu(acc) fp32, transposed [n][o]
        float* C = g_tt + (size_t)z * N2_ * CT_;
#pragma unroll
        for (int mt = 0; mt < 2; mt++) {
#pragma unroll
            for (int half = 0; half < 2; half++) {
                int row = m_w + mt * 16 + half * 8 + qrow;   // o
#pragma unroll
                for (int nt = 0; nt < 8; nt++) {
                    int col = nb + n_w + nt * 8 + qcol;      // n
                    C[(size_t)col * CT_ + row]       = fmaxf(d[mt][nt][half * 2],     0.f);
                    C[(size_t)(col + 1) * CT_ + row] = fmaxf(d[mt][nt][half * 2 + 1], 0.f);
                }
            }
        }
    }
}

// ---------------------------------------------------------------------------
// KNN + interp fused: phase 1 top-3 per query (256 queries / block),
// phase 2 gather-interp into g_bhi/g_blo cols 0..127.
// ---------------------------------------------------------------------------
__global__ __launch_bounds__(256) void k_knn_interp(
    const float* __restrict__ xyzs, const float* __restrict__ oxyzs)
{
    const int bt  = blockIdx.y;          // b*9 + (t1-1)
    const int bq  = bt / 9;
    const int t1  = bt % 9 + 1;
    const int qb  = blockIdx.x * 256;    // query base within bt
    const int tid = threadIdx.x;
    const int n   = qb + tid;

    int t2s[2], ks[2], nseg = 0;
    if ((t1 & 1) == 0) { t2s[0] = t1 / 2 - 1; ks[0] = 1; nseg = 1; }
    else {
        int p = (t1 - 1) >> 1;
        if (p - 1 >= 0) { t2s[nseg] = p - 1; ks[nseg] = 2; nseg++; }
        if (p <= 3)     { t2s[nseg] = p;     ks[nseg] = 0; nseg++; }
    }

    const float* q = oxyzs + ((size_t)bt * N1_ + n) * 3;
    const float qx = q[0], qy = q[1], qz = q[2];

    __shared__ float sr[3 * 1024];
    __shared__ float sw[256 * 3];
    __shared__ int   so[256 * 3];

    float b0 = 3.4e38f, b1 = 3.4e38f, b2 = 3.4e38f;
    int   o0 = 0, o1 = 0, o2 = 0;

    for (int s = 0; s < nseg; s++) {
        const float* sp = xyzs + (size_t)(bq * 4 + t2s[s]) * N2_ * 3;
        const int offbase = ((bq * 4 + t2s[s]) * 3 + ks[s]) * (N2_ * CT_);
        for (int base = 0; base < N2_; base += 1024) {
            __syncthreads();
#pragma unroll
            for (int t = tid; t < 3072; t += 256) sr[t] = sp[base * 3 + t];
            __syncthreads();
            for (int t = 0; t < 1024; t++) {
                float dx = qx - sr[3 * t];
                float dy = qy - sr[3 * t + 1];
                float dz = qz - sr[3 * t + 2];
                float dd = dx * dx + dy * dy + dz * dz;
                if (dd < b2) {
                    int off = offbase + (base + t) * CT_;
                    if (dd < b1) {
                        b2 = b1; o2 = o1;
                        if (dd < b0) { b1 = b0; o1 = o0; b0 = dd; o0 = off; }
                        else         { b1 = dd; o1 = off; }
                    } else { b2 = dd; o2 = off; }
                }
            }
        }
    }

    {
        float w0 = 1.f / (b0 + 1e-8f);
        float w1 = 1.f / (b1 + 1e-8f);
        float w2 = 1.f / (b2 + 1e-8f);
        float si = 1.f / (w0 + w1 + w2);
        sw[tid * 3]     = w0 * si;
        sw[tid * 3 + 1] = w1 * si;
        sw[tid * 3 + 2] = w2 * si;
        so[tid * 3]     = o0;
        so[tid * 3 + 1] = o1;
        so[tid * 3 + 2] = o2;
    }
    __syncthreads();

    // phase 2: 2 queries per iteration (tid>>7 selects half), c = tid&127
    const int half = tid >> 7;
    const int c    = tid & 127;
#pragma unroll 2
    for (int it = 0; it < 128; it++) {
        int ql = it + half * 128;
        float w0 = sw[ql * 3], w1 = sw[ql * 3 + 1], w2 = sw[ql * 3 + 2];
        int   p0 = so[ql * 3], p1 = so[ql * 3 + 1], p2 = so[ql * 3 + 2];
        float v = w0 * g_tt[p0 + c] + w1 * g_tt[p1 + c] + w2 * g_tt[p2 + c];
        bf16 hi, lo;
        split_bf16(v, hi, lo);
        size_t dd = ((size_t)bt * N1_ + qb + ql) * KD3_ + c;
        g_bhi[dd] = hi;
        g_blo[dd] = lo;
    }
}

// ---------------------------------------------------------------------------
// Stage 3 via mma.sync bf16 split-3 (unchanged from R4)
// ---------------------------------------------------------------------------
__global__ __launch_bounds__(512, 1) void k_mma3(
    const float* __restrict__ gamma, const float* __restrict__ beta,
    const float* __restrict__ mean,  const float* __restrict__ var,
    float* __restrict__ out)
{
    __shared__ __align__(128) char sA[256 * 128];
    __shared__ __align__(128) char sB[128 * 128];

    const int tid  = threadIdx.x;
    const int wid  = tid >> 5, lane = tid & 31;
    const int bt   = blockIdx.z;
    const int nb   = blockIdx.x * 128;
    const int m_w  = (wid & 7) * 32;
    const int n_w  = (wid >> 3) * 64;

    const uint32_t sa_b = smem_u32(sA);
    const uint32_t sb_b = smem_u32(sB);
    const size_t   brow = ((size_t)bt * N1_ + nb) * KD3_;

    float d[2][8][4];
#pragma unroll
    for (int mt = 0; mt < 2; mt++)
#pragma unroll
        for (int nt = 0; nt < 8; nt++)
#pragma unroll
            for (int r = 0; r < 4; r++) d[mt][nt][r] = 0.f;

    for (int chunk = 0; chunk < 9; chunk++) {
        const int p  = chunk / 3;
        const int k0 = (chunk % 3) * 64;
        const bf16* Asrc = (p < 2) ? g_whi : g_wlo;
        const bf16* Bsrc = (p == 1) ? g_blo : g_bhi;
        __syncthreads();
#pragma unroll
        for (int i = 0; i < 4; i++) {
            int idx = tid + i * 512;
            int m = idx >> 3, part = idx & 7;
            uint4 v = *(const uint4*)(Asrc + m * KD3_ + k0 + part * 8);
            *(uint4*)(sA + m * 128 + ((part * 16) ^ ((m & 7) << 4))) = v;
        }
#pragma unroll
        for (int i = 0; i < 2; i++) {
            int idx = tid + i * 512;
            int n = idx >> 3, part = idx & 7;
            uint4 v = *(const uint4*)(Bsrc + brow + (size_t)n * KD3_ + k0 + part * 8);
            *(uint4*)(sB + n * 128 + ((part * 16) ^ ((n & 7) << 4))) = v;
        }
        __syncthreads();

#pragma unroll
        for (int ks = 0; ks < 4; ks++) {
            uint32_t a[2][4];
#pragma unroll
            for (int mt = 0; mt < 2; mt++) {
                int m = m_w + mt * 16 + (lane & 15);
                uint32_t addr = sa_b + m * 128 +
                    (((uint32_t)(ks * 32 + (lane >> 4) * 16)) ^ ((m & 7) << 4));
                ldmx4(a[mt], addr);
            }
            uint32_t b[4][4];
#pragma unroll
            for (int pr = 0; pr < 4; pr++) {
                int n = n_w + pr * 16 + (lane >> 4) * 8 + (lane & 7);
                uint32_t addr = sb_b + n * 128 +
                    (((uint32_t)(ks * 32 + ((lane >> 3) & 1) * 16)) ^ ((n & 7) << 4));
                ldmx4(b[pr], addr);
            }
#pragma unroll
            for (int mt = 0; mt < 2; mt++)
#pragma unroll
                for (int nt = 0; nt < 8; nt++)
                    mma_bf16(d[mt][nt], a[mt], &b[nt >> 1][(nt & 1) * 2]);
        }
    }

    const int qrow = lane >> 2, qcol = (lane & 3) * 2;
#pragma unroll
    for (int mt = 0; mt < 2; mt++) {
#pragma unroll
        for (int half = 0; half < 2; half++) {
            int m = m_w + mt * 16 + half * 8 + qrow;
            float sc = gamma[m] * rsqrtf(var[m] + 1e-5f);
            float bi = beta[m] - mean[m] * sc;
            float* Cp = out + ((size_t)bt * CS_ + m) * N1_ + nb + n_w;
#pragma unroll
            for (int nt = 0; nt < 8; nt++) {
                float x = fmaxf(d[mt][nt][half * 2]     * sc + bi, 0.f);
                float y = fmaxf(d[mt][nt][half * 2 + 1] * sc + bi, 0.f);
                *(float2*)&Cp[nt * 8 + qcol] = make_float2(x, y);
            }
        }
    }
}

// ---------------------------------------------------------------------------
extern "C" void kernel_launch(void* const* d_in, const int* in_sizes, int n_in,
                              void* d_out, int out_size)
{
    const float* xyzs   = (const float*)d_in[0];
    const float* oxyzs  = (const float*)d_in[1];
    const float* feats  = (const float*)d_in[2];
    const float* ofeats = (const float*)d_in[3];
    const float* Wt0    = (const float*)d_in[4];
    const float* Wt1    = (const float*)d_in[5];
    const float* Ws     = (const float*)d_in[6];
    const float* gamma  = (const float*)d_in[7];
    const float* beta   = (const float*)d_in[8];
    const float* mean   = (const float*)d_in[9];
    const float* var    = (const float*)d_in[10];

    const int NEWF = B_ * L1_ * CS_ * N1_;
    int ofs = out_size - NEWF;
    float* outF = (float*)d_out;
    if (ofs > 0) {
        cudaMemcpyAsync(d_out, d_in[1], (size_t)ofs * sizeof(float),
                        cudaMemcpyDeviceToDevice, 0);   // node 1
        outF += ofs;
    }

    k_prep<<<PREP_W + PREP_F + PREP_OF, 256>>>(Wt0, Wt1, Ws, feats, ofeats); // 2
    k_hgemm<1><<<dim3(16, 1, 24), 256>>>();                                  // 3
    k_hgemm<2><<<dim3(16, 1, 24), 256>>>();                                  // 4
    k_knn_interp<<<dim3(32, 18), 256>>>(xyzs, oxyzs);                        // 5
    k_mma3<<<dim3(64, 1, 18), 512>>>(gamma, beta, mean, var, outF);          // 6 (profiled)
}